// round 1
// baseline (speedup 1.0000x reference)
#include <cuda_runtime.h>

#define NB        10000
#define SEQ       80
#define EMB       100
#define UNITS     64
#define ROWS      80        // batch rows per block -> grid = 125, exact
#define NTHREADS  256
#define RPT       5         // rows per thread (16 row-groups * 5 = 80)
#define HSTR      72        // h row stride (floats), 16B-aligned stores

// ---- dynamic shared memory layout (bytes) ----
#define SM_XBYTES (ROWS*EMB*4)                 // 32000 per x buffer
#define SM_X0     0
#define SM_X1     (SM_X0 + SM_XBYTES)
#define SM_WX     (SM_X1 + SM_XBYTES)          // 64000
#define SM_WH     (SM_WX + EMB*UNITS*4)        // +25600
#define SM_H      (SM_WH + UNITS*UNITS*4)      // +16384
#define SM_TOK    (SM_H  + ROWS*HSTR*4)        // +23040
#define SM_B      (SM_TOK + ROWS*SEQ*4)        // +25600
#define SM_WFC    (SM_B + 256)
#define SM_BFC    (SM_WFC + 256)
#define SMEM_TOTAL (SM_BFC + 16)               // ~155 KB

// ---- packed f32x2 helpers (sm_103a FFMA2: 2 MACs/instr, PTX-only) ----
__device__ __forceinline__ unsigned long long pack2(float x) {
    unsigned long long r;
    asm("mov.b64 %0, {%1, %1};" : "=l"(r) : "f"(x));
    return r;
}
__device__ __forceinline__ void fma2(unsigned long long& d,
                                     unsigned long long a,
                                     unsigned long long b) {
    asm("fma.rn.f32x2 %0, %1, %2, %0;" : "+l"(d) : "l"(a), "l"(b));
}
__device__ __forceinline__ float2 unpack2(unsigned long long v) {
    float2 f;
    asm("mov.b64 {%0, %1}, %2;" : "=f"(f.x), "=f"(f.y) : "l"(v));
    return f;
}

__global__ __launch_bounds__(NTHREADS, 1)
void rnn_fused_kernel(const int*   __restrict__ tokens,
                      const float* __restrict__ emb,
                      const float* __restrict__ Wx,
                      const float* __restrict__ Wh,
                      const float* __restrict__ bias,
                      const float* __restrict__ Wfc,
                      const float* __restrict__ bfc,
                      float*       __restrict__ out)
{
    extern __shared__ __align__(16) unsigned char smem_raw[];
    float* x_s[2];
    x_s[0]        = (float*)(smem_raw + SM_X0);
    x_s[1]        = (float*)(smem_raw + SM_X1);
    float* Wx_s   = (float*)(smem_raw + SM_WX);
    float* Wh_s   = (float*)(smem_raw + SM_WH);
    float* h_s    = (float*)(smem_raw + SM_H);
    int*   tok_s  = (int*)  (smem_raw + SM_TOK);   // layout [t][r]
    float* b_s    = (float*)(smem_raw + SM_B);
    float* wfc_s  = (float*)(smem_raw + SM_WFC);
    float* bfc_s  = (float*)(smem_raw + SM_BFC);

    const int tid  = threadIdx.x;
    const int row0 = blockIdx.x * ROWS;

    // ---- stage weights / tokens / init h ----
    for (int i = tid; i < EMB*UNITS; i += NTHREADS)   Wx_s[i] = Wx[i];
    for (int i = tid; i < UNITS*UNITS; i += NTHREADS) Wh_s[i] = Wh[i];
    if (tid < UNITS) { b_s[tid] = bias[tid]; wfc_s[tid] = Wfc[tid]; }
    if (tid == 0) bfc_s[0] = bfc[0];
    for (int i = tid; i < ROWS*SEQ; i += NTHREADS) {
        int r = i / SEQ, t = i % SEQ;
        tok_s[t*ROWS + r] = tokens[(row0 + r)*SEQ + t];   // transpose: [t][r]
    }
    for (int i = tid; i < ROWS*HSTR; i += NTHREADS) h_s[i] = 0.0f;
    __syncthreads();

    // ---- async x-tile loader: gather emb rows for step t into buffer ----
    auto load_x = [&](int buf, int t) {
        const int NT = ROWS * (EMB/4);   // 2000 x 16B transfers
        unsigned base = (unsigned)__cvta_generic_to_shared(x_s[buf]);
        #pragma unroll 2
        for (int i = tid; i < NT; i += NTHREADS) {
            int r = i / (EMB/4);
            int c = i % (EMB/4);
            int tok = tok_s[t*ROWS + r];
            const float* src = emb + tok*EMB + c*4;
            unsigned dst = base + (unsigned)((r*EMB + c*4)*4);
            asm volatile("cp.async.cg.shared.global [%0], [%1], 16;\n"
                         :: "r"(dst), "l"(src) : "memory");
        }
    };

    const int ug = tid & 15;        // 16 unit groups x 4 units
    const int rg = tid >> 4;        // 16 row groups x 5 rows
    const int u0 = ug * 4;
    const int rb = rg * RPT;

    const ulonglong2 b2 = *(const ulonglong2*)(b_s + u0);

    // prologue: prefetch step 0
    load_x(0, 0);
    asm volatile("cp.async.commit_group;\n" ::: "memory");

    for (int t = 0; t < SEQ; ++t) {
        if (t + 1 < SEQ) load_x((t+1) & 1, t+1);
        asm volatile("cp.async.commit_group;\n" ::: "memory");
        asm volatile("cp.async.wait_group 1;\n" ::: "memory");
        __syncthreads();   // x[t] ready; previous h stores visible

        const float* xb = x_s[t & 1];
        const float* xr0 = xb + (rb+0)*EMB;
        const float* xr1 = xb + (rb+1)*EMB;
        const float* xr2 = xb + (rb+2)*EMB;
        const float* xr3 = xb + (rb+3)*EMB;
        const float* xr4 = xb + (rb+4)*EMB;

        unsigned long long a0[RPT], a1[RPT];
        #pragma unroll
        for (int i = 0; i < RPT; ++i) { a0[i] = b2.x; a1[i] = b2.y; }

        // x @ Wx
        #pragma unroll 4
        for (int e = 0; e < EMB; ++e) {
            ulonglong2 w = *(const ulonglong2*)(Wx_s + e*UNITS + u0);
            unsigned long long xx;
            xx = pack2(xr0[e]); fma2(a0[0], xx, w.x); fma2(a1[0], xx, w.y);
            xx = pack2(xr1[e]); fma2(a0[1], xx, w.x); fma2(a1[1], xx, w.y);
            xx = pack2(xr2[e]); fma2(a0[2], xx, w.x); fma2(a1[2], xx, w.y);
            xx = pack2(xr3[e]); fma2(a0[3], xx, w.x); fma2(a1[3], xx, w.y);
            xx = pack2(xr4[e]); fma2(a0[4], xx, w.x); fma2(a1[4], xx, w.y);
        }

        // h @ Wh
        const float* hr0 = h_s + (rb+0)*HSTR;
        const float* hr1 = h_s + (rb+1)*HSTR;
        const float* hr2 = h_s + (rb+2)*HSTR;
        const float* hr3 = h_s + (rb+3)*HSTR;
        const float* hr4 = h_s + (rb+4)*HSTR;
        #pragma unroll 4
        for (int v = 0; v < UNITS; ++v) {
            ulonglong2 w = *(const ulonglong2*)(Wh_s + v*UNITS + u0);
            unsigned long long hh;
            hh = pack2(hr0[v]); fma2(a0[0], hh, w.x); fma2(a1[0], hh, w.y);
            hh = pack2(hr1[v]); fma2(a0[1], hh, w.x); fma2(a1[1], hh, w.y);
            hh = pack2(hr2[v]); fma2(a0[2], hh, w.x); fma2(a1[2], hh, w.y);
            hh = pack2(hr3[v]); fma2(a0[3], hh, w.x); fma2(a1[3], hh, w.y);
            hh = pack2(hr4[v]); fma2(a0[4], hh, w.x); fma2(a1[4], hh, w.y);
        }

        // tanh -> new h
        float4 hn[RPT];
        #pragma unroll
        for (int i = 0; i < RPT; ++i) {
            float2 lo = unpack2(a0[i]);
            float2 hi = unpack2(a1[i]);
            hn[i].x = tanhf(lo.x);
            hn[i].y = tanhf(lo.y);
            hn[i].z = tanhf(hi.x);
            hn[i].w = tanhf(hi.y);
        }
        __syncthreads();   // everyone done reading old h
        #pragma unroll
        for (int i = 0; i < RPT; ++i)
            *(float4*)(h_s + (rb+i)*HSTR + u0) = hn[i];
    }
    __syncthreads();

    // ---- final FC + sigmoid: one thread per row ----
    if (tid < ROWS) {
        const float* hr = h_s + tid*HSTR;
        float dot = 0.0f;
        #pragma unroll 8
        for (int v = 0; v < UNITS; ++v) dot += hr[v] * wfc_s[v];
        float logit = dot + bfc_s[0];
        out[row0 + tid] = 1.0f / (1.0f + expf(-logit));
    }
}

extern "C" void kernel_launch(void* const* d_in, const int* in_sizes, int n_in,
                              void* d_out, int out_size) {
    const int*   tokens = (const int*)  d_in[0];
    const float* emb    = (const float*)d_in[1];
    const float* Wx     = (const float*)d_in[2];
    const float* Wh     = (const float*)d_in[3];
    const float* b      = (const float*)d_in[4];
    const float* Wfc    = (const float*)d_in[5];
    const float* bfc    = (const float*)d_in[6];
    float* out          = (float*)d_out;

    static bool attr_set = false;
    // idempotent + deterministic; not a stream op, safe under graph capture
    cudaFuncSetAttribute(rnn_fused_kernel,
                         cudaFuncAttributeMaxDynamicSharedMemorySize,
                         SMEM_TOTAL);
    (void)attr_set;

    dim3 grid(NB / ROWS);   // 125 blocks, exact tiling, no bounds checks
    rnn_fused_kernel<<<grid, NTHREADS, SMEM_TOTAL>>>(
        tokens, emb, Wx, Wh, b, Wfc, bfc, out);
}

// round 2
// speedup vs baseline: 1.0814x; 1.0814x over previous
#include <cuda_runtime.h>

#define NB        10000
#define SEQ       80
#define EMB       100
#define UNITS     64
#define ROWS      80          // batch rows per block -> grid = 125 exact
#define NTHREADS  320         // 16 unit-groups x 20 row-groups
#define HSTR      68          // h row stride (floats): 272B, 16B-aligned, mod128=16
#define NE2       50          // EMB/2 k-pairs
#define NV2       32          // UNITS/2 k-pairs
#define NK        (NE2+NV2)   // 82 paired entries per unit column
#define WCOL_STRIDE 2704      // bytes per ug column: 82*32=2624 padded; 2704 % 128 == 16

// ---- shared memory layout (bytes) ----
#define SM_X0   0
#define SM_X1   32000                       // ROWS*EMB*4
#define SM_W    64000
#define SM_H    (SM_W + 16*WCOL_STRIDE)     // 64000 + 43264 = 107264
#define SM_TOK  (SM_H + ROWS*HSTR*4)        // +21760 = 129024
#define SMEM_TOTAL (SM_TOK + ROWS*SEQ*4 + 64)   // ~154.7 KB

typedef unsigned long long u64;

// packed f32x2 FMA: d.lo += a.lo*b.lo ; d.hi += a.hi*b.hi
__device__ __forceinline__ void fma2(u64& d, u64 a, u64 b) {
    asm("fma.rn.f32x2 %0, %1, %2, %0;" : "+l"(d) : "l"(a), "l"(b));
}
// fold even/odd partial sums and apply fast tanh
__device__ __forceinline__ float fold_tanh(u64 v) {
    float lo, hi;
    asm("mov.b64 {%0, %1}, %2;" : "=f"(lo), "=f"(hi) : "l"(v));
    float s = lo + hi;
    float r;
    asm("tanh.approx.f32 %0, %1;" : "=f"(r) : "f"(s));
    return r;
}

__global__ __launch_bounds__(NTHREADS, 1)
void rnn_fused2(const int*   __restrict__ tokens,
                const float* __restrict__ emb,
                const float* __restrict__ Wx,
                const float* __restrict__ Wh,
                const float* __restrict__ bias,
                const float* __restrict__ Wfc,
                const float* __restrict__ bfc,
                float*       __restrict__ out)
{
    extern __shared__ __align__(16) unsigned char smem[];
    float* x_s[2] = { (float*)(smem + SM_X0), (float*)(smem + SM_X1) };
    unsigned char* wbase = smem + SM_W;
    float* h_s   = (float*)(smem + SM_H);
    int*   tok_s = (int*)  (smem + SM_TOK);   // [t][r]

    const int tid  = threadIdx.x;
    const int row0 = blockIdx.x * ROWS;

    // ---- stage tokens transposed [t][r] ----
    for (int i = tid; i < ROWS*SEQ; i += NTHREADS) {
        int r = i / SEQ, t = i - r*SEQ;
        tok_s[t*ROWS + r] = tokens[(row0 + r)*SEQ + t];
    }
    // ---- build per-unit-group weight columns of k-paired u64 entries ----
    // entry layout: wcol(ug)[k*32 + j*8] = {W[2k][4ug+j], W[2k+1][4ug+j]}
    for (int i = tid; i < 16*NK*4; i += NTHREADS) {
        int ug  = i / (NK*4);
        int rem = i - ug*(NK*4);
        int k   = rem >> 2;
        int j   = rem & 3;
        int u   = ug*4 + j;
        float lo, hi;
        if (k < NE2) { lo = Wx[(2*k)*UNITS + u];        hi = Wx[(2*k+1)*UNITS + u]; }
        else { int v = k - NE2; lo = Wh[(2*v)*UNITS + u]; hi = Wh[(2*v+1)*UNITS + u]; }
        *(float2*)(wbase + ug*WCOL_STRIDE + k*32 + j*8) = make_float2(lo, hi);
    }
    // ---- zero h ----
    for (int i = tid; i < ROWS*HSTR; i += NTHREADS) h_s[i] = 0.0f;
    __syncthreads();

    const int ug = tid & 15;
    const int rg = tid >> 4;
    const int u0 = ug * 4;
    const int rb = rg * 4;
    const unsigned char* wcol = wbase + ug*WCOL_STRIDE;

    // bias packed into lo lane only (hi folds to +0)
    u64 binit[4];
    #pragma unroll
    for (int j = 0; j < 4; ++j) {
        float bj = bias[u0 + j];
        asm("mov.b64 %0, {%1, %2};" : "=l"(binit[j]) : "f"(bj), "f"(0.0f));
    }

    // ---- async x-tile gather: emb rows for step t (row-major [r][e]) ----
    auto load_x = [&](int buf, int t) {
        unsigned base = (unsigned)__cvta_generic_to_shared(x_s[buf]);
        #pragma unroll
        for (int kk = 0; kk < 7; ++kk) {
            int i = tid + kk*NTHREADS;
            if (i < ROWS*25) {
                int r = i / 25;
                int c = i - r*25;
                int tk = tok_s[t*ROWS + r];
                const float* src = emb + tk*EMB + c*4;
                unsigned dst = base + (unsigned)((r*EMB + c*4)*4);
                asm volatile("cp.async.cg.shared.global [%0], [%1], 16;"
                             :: "r"(dst), "l"(src));
            }
        }
    };

    load_x(0, 0);
    asm volatile("cp.async.commit_group;" ::: "memory");

    for (int t = 0; t < SEQ; ++t) {
        if (t + 1 < SEQ) load_x((t+1)&1, t+1);
        asm volatile("cp.async.commit_group;" ::: "memory");
        asm volatile("cp.async.wait_group 1;" ::: "memory");
        __syncthreads();     // x[t] ready; previous step's h stores visible

        u64 acc[4][4];
        #pragma unroll
        for (int i = 0; i < 4; ++i)
            #pragma unroll
            for (int j = 0; j < 4; ++j) acc[i][j] = binit[j];

        const float* xb = x_s[t & 1];
        const float* xr[4] = { xb + (rb+0)*EMB, xb + (rb+1)*EMB,
                               xb + (rb+2)*EMB, xb + (rb+3)*EMB };

        // ---- x @ Wx : k split across f32x2 lanes, 2 k-pairs per iter ----
        #pragma unroll 5
        for (int e2 = 0; e2 < NE2; e2 += 2) {
            ulonglong2 wa0 = *(const ulonglong2*)(wcol + e2*32);        // e2:   u0,u0+1
            ulonglong2 wb0 = *(const ulonglong2*)(wcol + e2*32 + 16);   // e2:   u0+2,u0+3
            ulonglong2 wa1 = *(const ulonglong2*)(wcol + e2*32 + 32);   // e2+1: u0,u0+1
            ulonglong2 wb1 = *(const ulonglong2*)(wcol + e2*32 + 48);   // e2+1: u0+2,u0+3
            #pragma unroll
            for (int i = 0; i < 4; ++i) {
                ulonglong2 xv = *(const ulonglong2*)(xr[i] + 2*e2);     // pairs e2, e2+1
                fma2(acc[i][0], xv.x, wa0.x); fma2(acc[i][1], xv.x, wa0.y);
                fma2(acc[i][2], xv.x, wb0.x); fma2(acc[i][3], xv.x, wb0.y);
                fma2(acc[i][0], xv.y, wa1.x); fma2(acc[i][1], xv.y, wa1.y);
                fma2(acc[i][2], xv.y, wb1.x); fma2(acc[i][3], xv.y, wb1.y);
            }
        }

        // ---- h @ Wh : same trick over v pairs ----
        const float* hr[4] = { h_s + (rb+0)*HSTR, h_s + (rb+1)*HSTR,
                               h_s + (rb+2)*HSTR, h_s + (rb+3)*HSTR };
        const unsigned char* wcolh = wcol + NE2*32;
        #pragma unroll 4
        for (int v2 = 0; v2 < NV2; v2 += 2) {
            ulonglong2 wa0 = *(const ulonglong2*)(wcolh + v2*32);
            ulonglong2 wb0 = *(const ulonglong2*)(wcolh + v2*32 + 16);
            ulonglong2 wa1 = *(const ulonglong2*)(wcolh + v2*32 + 32);
            ulonglong2 wb1 = *(const ulonglong2*)(wcolh + v2*32 + 48);
            #pragma unroll
            for (int i = 0; i < 4; ++i) {
                ulonglong2 hv = *(const ulonglong2*)(hr[i] + 2*v2);
                fma2(acc[i][0], hv.x, wa0.x); fma2(acc[i][1], hv.x, wa0.y);
                fma2(acc[i][2], hv.x, wb0.x); fma2(acc[i][3], hv.x, wb0.y);
                fma2(acc[i][0], hv.y, wa1.x); fma2(acc[i][1], hv.y, wa1.y);
                fma2(acc[i][2], hv.y, wb1.x); fma2(acc[i][3], hv.y, wb1.y);
            }
        }

        // ---- fold + tanh -> new h ----
        float4 hn[4];
        #pragma unroll
        for (int i = 0; i < 4; ++i) {
            hn[i].x = fold_tanh(acc[i][0]);
            hn[i].y = fold_tanh(acc[i][1]);
            hn[i].z = fold_tanh(acc[i][2]);
            hn[i].w = fold_tanh(acc[i][3]);
        }
        __syncthreads();     // all reads of old h done
        #pragma unroll
        for (int i = 0; i < 4; ++i)
            *(float4*)(h_s + (rb+i)*HSTR + u0) = hn[i];
    }
    __syncthreads();

    // ---- final FC + sigmoid: one thread per row ----
    if (tid < ROWS) {
        const float* hrw = h_s + tid*HSTR;
        float dot = 0.0f;
        #pragma unroll 8
        for (int v = 0; v < UNITS; ++v) dot += hrw[v] * Wfc[v];
        float logit = dot + bfc[0];
        out[row0 + tid] = 1.0f / (1.0f + __expf(-logit));
    }
}

extern "C" void kernel_launch(void* const* d_in, const int* in_sizes, int n_in,
                              void* d_out, int out_size) {
    const int*   tokens = (const int*)  d_in[0];
    const float* emb    = (const float*)d_in[1];
    const float* Wx     = (const float*)d_in[2];
    const float* Wh     = (const float*)d_in[3];
    const float* b      = (const float*)d_in[4];
    const float* Wfc    = (const float*)d_in[5];
    const float* bfc    = (const float*)d_in[6];
    float* out          = (float*)d_out;

    cudaFuncSetAttribute(rnn_fused2,
                         cudaFuncAttributeMaxDynamicSharedMemorySize,
                         SMEM_TOTAL);

    dim3 grid(NB / ROWS);   // 125 blocks, exact tiling
    rnn_fused2<<<grid, NTHREADS, SMEM_TOTAL>>>(
        tokens, emb, Wx, Wh, b, Wfc, bfc, out);
}

// round 4
// speedup vs baseline: 2.1848x; 2.0203x over previous
#include <cuda_runtime.h>

#define NB        10000
#define VOCAB     10000
#define SEQ       80
#define EMB       100
#define UNITS     64
#define ROWS      80          // batch rows per block -> grid = 125 exact
#define NTHREADS  320         // 16 unit-groups x 20 row-groups
#define HSTR      68          // h/xp row stride (floats)
#define NV2       32          // UNITS/2 k-pairs for the recurrent matmul
#define WSTR      1040        // bytes per unit-group weight column (32*32=1024 + pad)

// precomputed ETable[v][u] = emb[v] @ Wx[:,u] + b[u]
__device__ float g_etable[VOCAB * UNITS];

// ---- shared memory layout (bytes) ----
#define TILE_B   (ROWS*HSTR*4)            // 21760
#define SM_XP0   0
#define SM_XP1   (SM_XP0 + TILE_B)
#define SM_W     (SM_XP1 + TILE_B)        // 43520
#define SM_H0    (SM_W + 16*WSTR)         // +16640 = 60160
#define SM_H1    (SM_H0 + TILE_B)         // 81920
#define SM_TOK   (SM_H1 + TILE_B)         // 103680
#define SMEM_TOTAL (SM_TOK + ROWS*SEQ*4 + 64)   // ~129.3 KB

typedef unsigned long long u64;

__device__ __forceinline__ void fma2(u64& d, u64 a, u64 b) {
    asm("fma.rn.f32x2 %0, %1, %2, %0;" : "+l"(d) : "l"(a), "l"(b));
}
__device__ __forceinline__ u64 pack_lo(float x) {
    u64 r; asm("mov.b64 %0, {%1, %2};" : "=l"(r) : "f"(x), "f"(0.0f)); return r;
}
__device__ __forceinline__ float fold_tanh(u64 v) {
    float lo, hi;
    asm("mov.b64 {%0, %1}, %2;" : "=f"(lo), "=f"(hi) : "l"(v));
    float s = lo + hi, r;
    asm("tanh.approx.f32 %0, %1;" : "=f"(r) : "f"(s));
    return r;
}

// ============ kernel 1: ETable = emb @ Wx + b  (64M MACs, one-shot) ============
__global__ __launch_bounds__(256)
void build_etable(const float* __restrict__ emb,
                  const float* __restrict__ Wx,
                  const float* __restrict__ bias)
{
    const int w   = threadIdx.x >> 5;
    const int l   = threadIdx.x & 31;
    const int row = blockIdx.x * 8 + w;     // 1250 blocks * 8 rows = 10000 exact
    const int u   = l * 2;
    float2 acc = make_float2(bias[u], bias[u + 1]);
    const float* er = emb + row * EMB;
    #pragma unroll 4
    for (int e = 0; e < EMB; ++e) {
        float xe = __ldg(er + e);
        float2 wv = *(const float2*)(Wx + e * UNITS + u);
        acc.x = fmaf(xe, wv.x, acc.x);
        acc.y = fmaf(xe, wv.y, acc.y);
    }
    *(float2*)(g_etable + row * UNITS + u) = acc;
}

// ============ kernel 2: fused recurrent scan ============
__global__ __launch_bounds__(NTHREADS, 1)
void rnn_scan(const int*   __restrict__ tokens,
              const float* __restrict__ Wh,
              const float* __restrict__ Wfc,
              const float* __restrict__ bfc,
              float*       __restrict__ out)
{
    extern __shared__ __align__(16) unsigned char smem[];
    float* xp_s[2] = { (float*)(smem + SM_XP0), (float*)(smem + SM_XP1) };
    unsigned char* wbase = smem + SM_W;
    float* h_sb[2] = { (float*)(smem + SM_H0), (float*)(smem + SM_H1) };
    int*   tok_s   = (int*)(smem + SM_TOK);   // [t][r]

    const int tid  = threadIdx.x;
    const int row0 = blockIdx.x * ROWS;

    // ---- stage tokens transposed [t][r] ----
    for (int i = tid; i < ROWS * SEQ; i += NTHREADS) {
        int r = i / SEQ, t = i - r * SEQ;
        tok_s[t * ROWS + r] = tokens[(row0 + r) * SEQ + t];
    }
    // ---- k-paired Wh columns per unit-group ----
    // wcol(ug)[k*32 + j*8] = {Wh[2k][4ug+j], Wh[2k+1][4ug+j]}
    for (int i = tid; i < 16 * NV2 * 4; i += NTHREADS) {
        int ug  = i / (NV2 * 4);
        int rem = i - ug * (NV2 * 4);
        int k   = rem >> 2;
        int j   = rem & 3;
        int u   = ug * 4 + j;
        *(float2*)(wbase + ug * WSTR + k * 32 + j * 8) =
            make_float2(Wh[(2 * k) * UNITS + u], Wh[(2 * k + 1) * UNITS + u]);
    }
    // ---- zero h buffer 0 (read at t=0) ----
    for (int i = tid; i < ROWS * HSTR; i += NTHREADS) h_sb[0][i] = 0.0f;

    const int ug = tid & 15;
    const int rg = tid >> 4;
    const int u0 = ug * 4;
    const int rb = rg * 4;
    const unsigned char* wcol = wbase + ug * WSTR;

    // xp gather: 80 rows x 16 chunks of 16B = 1280 transfers -> 4 per thread
    auto load_xp = [&](int buf, int t) {
        unsigned base = (unsigned)__cvta_generic_to_shared(xp_s[buf]);
        #pragma unroll
        for (int k = 0; k < 4; ++k) {
            int i = tid + k * NTHREADS;      // 0..1279
            int r = i >> 4;                  // row 0..79
            int c = i & 15;                  // chunk 0..15 (units c*4..c*4+3)
            int tk = tok_s[t * ROWS + r];
            const float* src = g_etable + tk * UNITS + c * 4;
            unsigned dst = base + (unsigned)((r * HSTR + c * 4) * 4);
            asm volatile("cp.async.cg.shared.global [%0], [%1], 16;"
                         :: "r"(dst), "l"(src));
        }
        asm volatile("cp.async.commit_group;" ::: "memory");
    };

    __syncthreads();                // tokens/weights/h0 staged
    load_xp(0, 0);

    for (int t = 0; t < SEQ; ++t) {
        asm volatile("cp.async.wait_group 0;" ::: "memory");
        __syncthreads();
        // barrier semantics: all reads of xp[t-1]/h[t-1] happened before this
        // point; all writes to the buffers they lived in happen after it.
        if (t + 1 < SEQ) load_xp((t + 1) & 1, t + 1);

        const float* xp = xp_s[t & 1];
        const float* hr = h_sb[t & 1];
        float*       hw = h_sb[(t + 1) & 1];

        // init accumulators from gathered xp (bias already folded into ETable)
        u64 acc[4][4];
        #pragma unroll
        for (int i = 0; i < 4; ++i) {
            float4 v = *(const float4*)(xp + (rb + i) * HSTR + u0);
            acc[i][0] = pack_lo(v.x);
            acc[i][1] = pack_lo(v.y);
            acc[i][2] = pack_lo(v.z);
            acc[i][3] = pack_lo(v.w);
        }

        const float* hr0 = hr + (rb + 0) * HSTR;
        const float* hr1 = hr + (rb + 1) * HSTR;
        const float* hr2 = hr + (rb + 2) * HSTR;
        const float* hr3 = hr + (rb + 3) * HSTR;

        // ---- h @ Wh : k split across f32x2 lanes, 2 k-pairs per iter ----
        #pragma unroll 4
        for (int v2 = 0; v2 < NV2; v2 += 2) {
            ulonglong2 wa0 = *(const ulonglong2*)(wcol + v2 * 32);
            ulonglong2 wb0 = *(const ulonglong2*)(wcol + v2 * 32 + 16);
            ulonglong2 wa1 = *(const ulonglong2*)(wcol + v2 * 32 + 32);
            ulonglong2 wb1 = *(const ulonglong2*)(wcol + v2 * 32 + 48);

            ulonglong2 h0 = *(const ulonglong2*)(hr0 + 2 * v2);
            ulonglong2 h1 = *(const ulonglong2*)(hr1 + 2 * v2);
            ulonglong2 h2 = *(const ulonglong2*)(hr2 + 2 * v2);
            ulonglong2 h3 = *(const ulonglong2*)(hr3 + 2 * v2);

            fma2(acc[0][0], h0.x, wa0.x); fma2(acc[0][1], h0.x, wa0.y);
            fma2(acc[0][2], h0.x, wb0.x); fma2(acc[0][3], h0.x, wb0.y);
            fma2(acc[0][0], h0.y, wa1.x); fma2(acc[0][1], h0.y, wa1.y);
            fma2(acc[0][2], h0.y, wb1.x); fma2(acc[0][3], h0.y, wb1.y);

            fma2(acc[1][0], h1.x, wa0.x); fma2(acc[1][1], h1.x, wa0.y);
            fma2(acc[1][2], h1.x, wb0.x); fma2(acc[1][3], h1.x, wb0.y);
            fma2(acc[1][0], h1.y, wa1.x); fma2(acc[1][1], h1.y, wa1.y);
            fma2(acc[1][2], h1.y, wb1.x); fma2(acc[1][3], h1.y, wb1.y);

            fma2(acc[2][0], h2.x, wa0.x); fma2(acc[2][1], h2.x, wa0.y);
            fma2(acc[2][2], h2.x, wb0.x); fma2(acc[2][3], h2.x, wb0.y);
            fma2(acc[2][0], h2.y, wa1.x); fma2(acc[2][1], h2.y, wa1.y);
            fma2(acc[2][2], h2.y, wb1.x); fma2(acc[2][3], h2.y, wb1.y);

            fma2(acc[3][0], h3.x, wa0.x); fma2(acc[3][1], h3.x, wa0.y);
            fma2(acc[3][2], h3.x, wb0.x); fma2(acc[3][3], h3.x, wb0.y);
            fma2(acc[3][0], h3.y, wa1.x); fma2(acc[3][1], h3.y, wa1.y);
            fma2(acc[3][2], h3.y, wb1.x); fma2(acc[3][3], h3.y, wb1.y);
        }

        // ---- fold + tanh -> write new h to the other buffer (no 2nd sync) ----
        #pragma unroll
        for (int i = 0; i < 4; ++i) {
            float4 hn;
            hn.x = fold_tanh(acc[i][0]);
            hn.y = fold_tanh(acc[i][1]);
            hn.z = fold_tanh(acc[i][2]);
            hn.w = fold_tanh(acc[i][3]);
            *(float4*)(hw + (rb + i) * HSTR + u0) = hn;
        }
    }
    __syncthreads();

    // ---- final FC + sigmoid (final h lives in buffer SEQ&1 = 0) ----
    if (tid < ROWS) {
        const float* hf = h_sb[SEQ & 1] + tid * HSTR;
        float dot = 0.0f;
        #pragma unroll 8
        for (int v = 0; v < UNITS; ++v) dot += hf[v] * Wfc[v];
        float logit = dot + bfc[0];
        out[row0 + tid] = 1.0f / (1.0f + __expf(-logit));
    }
}

extern "C" void kernel_launch(void* const* d_in, const int* in_sizes, int n_in,
                              void* d_out, int out_size) {
    const int*   tokens = (const int*)  d_in[0];
    const float* emb    = (const float*)d_in[1];
    const float* Wx     = (const float*)d_in[2];
    const float* Wh     = (const float*)d_in[3];
    const float* b      = (const float*)d_in[4];
    const float* Wfc    = (const float*)d_in[5];
    const float* bfc    = (const float*)d_in[6];
    float* out          = (float*)d_out;

    cudaFuncSetAttribute(rnn_scan,
                         cudaFuncAttributeMaxDynamicSharedMemorySize,
                         SMEM_TOTAL);

    build_etable<<<VOCAB / 8, 256>>>(emb, Wx, b);
    rnn_scan<<<NB / ROWS, NTHREADS, SMEM_TOTAL>>>(tokens, Wh, Wfc, bfc, out);
}

// round 5
// speedup vs baseline: 2.8914x; 1.3234x over previous
#include <cuda_runtime.h>

#define NB        10000
#define VOCAB     10000
#define SEQ       80
#define EMB       100
#define UNITS     64
#define WARPS     10
#define RPW       8           // rows per warp
#define ROWS      (WARPS*RPW) // 80 rows per block -> grid = 125 exact
#define NTHREADS  (WARPS*32)
#define NV2       32          // UNITS/2 k-pairs

// precomputed ETable[v][u] = emb[v] @ Wx[:,u] + b[u]
__device__ float g_etable[VOCAB * UNITS];

typedef unsigned long long u64;

__device__ __forceinline__ void fma2(u64& d, u64 a, u64 b) {
    asm("fma.rn.f32x2 %0, %1, %2, %0;" : "+l"(d) : "l"(a), "l"(b));
}
__device__ __forceinline__ u64 packf2(float lo, float hi) {
    u64 r; asm("mov.b64 %0, {%1, %2};" : "=l"(r) : "f"(lo), "f"(hi)); return r;
}
__device__ __forceinline__ float fold_tanh(u64 v) {
    float lo, hi;
    asm("mov.b64 {%0, %1}, %2;" : "=f"(lo), "=f"(hi) : "l"(v));
    float s = lo + hi, r;
    asm("tanh.approx.f32 %0, %1;" : "=f"(r) : "f"(s));
    return r;
}

// ============ kernel 1: ETable = emb @ Wx + b (one-shot, 64M MACs) ============
__global__ __launch_bounds__(256)
void build_etable(const float* __restrict__ emb,
                  const float* __restrict__ Wx,
                  const float* __restrict__ bias)
{
    const int w   = threadIdx.x >> 5;
    const int l   = threadIdx.x & 31;
    const int row = blockIdx.x * 8 + w;     // 1250 blocks * 8 = 10000 exact
    const int u   = l * 2;
    float2 acc = make_float2(bias[u], bias[u + 1]);
    const float* er = emb + row * EMB;
    #pragma unroll 4
    for (int e = 0; e < EMB; ++e) {
        float xe = __ldg(er + e);
        float2 wv = *(const float2*)(Wx + e * UNITS + u);
        acc.x = fmaf(xe, wv.x, acc.x);
        acc.y = fmaf(xe, wv.y, acc.y);
    }
    *(float2*)(g_etable + row * UNITS + u) = acc;
}

// ============ kernel 2: warp-private recurrent scan, Wh in registers ============
__global__ __launch_bounds__(NTHREADS, 1)
void rnn_scan(const int* __restrict__ tokens,
              const float* __restrict__ Wh,
              const float* __restrict__ Wfc,
              const float* __restrict__ bfc,
              float* __restrict__ out)
{
    __shared__ int   tok_s[WARPS][SEQ][RPW];    // [warp][t][r]  25600 B
    __shared__ float h_s[WARPS][RPW][UNITS];    // [warp][row][unit] 20480 B

    const int tid  = threadIdx.x;
    const int w    = tid >> 5;
    const int l    = tid & 31;
    const int row0 = blockIdx.x * ROWS + w * RPW;

    // ---- stage this warp's tokens (transposed [t][r]) ----
    for (int i = l; i < SEQ * RPW; i += 32) {
        int t = i >> 3, r = i & 7;
        tok_s[w][t][r] = tokens[(row0 + r) * SEQ + t];
    }
    // ---- zero this warp's h ----
    for (int i = l; i < RPW * UNITS; i += 32)
        ((float*)h_s[w])[i] = 0.0f;

    // ---- Wh columns for units (2l, 2l+1), k-paired, into registers ----
    // wu0[k2] = {Wh[2k2][2l],   Wh[2k2+1][2l]}
    // wu1[k2] = {Wh[2k2][2l+1], Wh[2k2+1][2l+1]}
    u64 wu0[NV2], wu1[NV2];
    {
        const int u0 = 2 * l;
        #pragma unroll
        for (int k2 = 0; k2 < NV2; ++k2) {
            float2 a = *(const float2*)(Wh + (2 * k2)     * UNITS + u0);
            float2 b = *(const float2*)(Wh + (2 * k2 + 1) * UNITS + u0);
            wu0[k2] = packf2(a.x, b.x);
            wu1[k2] = packf2(a.y, b.y);
        }
    }
    __syncwarp();

    // ---- prefetch xp for t=0: coalesced LDG.64 per row ----
    u64 xpre[RPW];
    #pragma unroll
    for (int r = 0; r < RPW; ++r) {
        int tk = tok_s[w][0][r];                        // uniform across warp
        xpre[r] = *(const u64*)(g_etable + tk * UNITS + 2 * l);
    }

    for (int t = 0; t < SEQ; ++t) {
        // init accumulators from prefetched xp (bias folded into ETable)
        // k-split: lo lane accumulates even-k partials, hi lane odd-k
        u64 acc[RPW][2];
        #pragma unroll
        for (int r = 0; r < RPW; ++r) {
            float f0, f1;
            asm("mov.b64 {%0, %1}, %2;" : "=f"(f0), "=f"(f1) : "l"(xpre[r]));
            acc[r][0] = packf2(f0, 0.0f);
            acc[r][1] = packf2(f1, 0.0f);
        }

        // prefetch next step's xp (clamped at the end; extra load discarded)
        const int tn = (t + 1 < SEQ) ? (t + 1) : (SEQ - 1);
        #pragma unroll
        for (int r = 0; r < RPW; ++r) {
            int tk = tok_s[w][tn][r];
            xpre[r] = *(const u64*)(g_etable + tk * UNITS + 2 * l);
        }

        // ---- h @ Wh: h pairs broadcast from SMEM, weights from registers ----
        #pragma unroll
        for (int j = 0; j < 16; ++j) {          // 4 h values = k-pairs 2j, 2j+1
            #pragma unroll
            for (int r = 0; r < RPW; ++r) {
                ulonglong2 hv = *(const ulonglong2*)(&h_s[w][r][4 * j]); // broadcast
                fma2(acc[r][0], hv.x, wu0[2 * j]);
                fma2(acc[r][1], hv.x, wu1[2 * j]);
                fma2(acc[r][0], hv.y, wu0[2 * j + 1]);
                fma2(acc[r][1], hv.y, wu1[2 * j + 1]);
            }
        }

        __syncwarp();   // all broadcast reads of h done before overwrite
        #pragma unroll
        for (int r = 0; r < RPW; ++r) {
            float f0 = fold_tanh(acc[r][0]);
            float f1 = fold_tanh(acc[r][1]);
            *(u64*)(&h_s[w][r][2 * l]) = packf2(f0, f1);   // STS.64, coalesced
        }
        __syncwarp();   // new h visible to all lanes before next step's reads
    }

    // ---- final FC + sigmoid: lanes 0..7 each handle one row ----
    if (l < RPW) {
        const float* hf = h_s[w][l];
        float dot = 0.0f;
        #pragma unroll 8
        for (int v = 0; v < UNITS; ++v) dot += hf[v] * __ldg(Wfc + v);
        float logit = dot + __ldg(bfc);
        out[row0 + l] = 1.0f / (1.0f + __expf(-logit));
    }
}

extern "C" void kernel_launch(void* const* d_in, const int* in_sizes, int n_in,
                              void* d_out, int out_size) {
    const int*   tokens = (const int*)  d_in[0];
    const float* emb    = (const float*)d_in[1];
    const float* Wx     = (const float*)d_in[2];
    const float* Wh     = (const float*)d_in[3];
    const float* b      = (const float*)d_in[4];
    const float* Wfc    = (const float*)d_in[5];
    const float* bfc    = (const float*)d_in[6];
    float* out          = (float*)d_out;

    build_etable<<<VOCAB / 8, 256>>>(emb, Wx, b);
    rnn_scan<<<NB / ROWS, NTHREADS>>>(tokens, Wh, Wfc, bfc, out);
}